// round 4
// baseline (speedup 1.0000x reference)
#include <cuda_runtime.h>
#include <cstdint>
#include <cstddef>

// Legacy-path (mma.sync m16n8k8.tf32) fused NeuralCTLSTM, v2:
// 2 CTAs/SM. BM=128, BO=8, W block (7x8x256 = 56KB) resident+pre-permuted,
// A 3-stage cp.async ring with 1 syncthreads/chunk and 2-deep prefetch.
// Persistent grid 32 x 9 = 288 CTAs (all resident), ~57 b-tiles each.

#define NG 7
#define HH 256
#define BM 128
#define BO 8
#define BK 32
#define NCHUNK 8
#define THREADS 256
#define GYS 9

#define SSTR 36                               // padded A row stride (floats)
#define W_BYTES (NG * NCHUNK * 2 * 512)       // 112 frag-units x 512B = 57344
#define A_STAGE_BYTES (BM * SSTR * 4)         // 18432
#define OFF_A W_BYTES
#define SMEM_BYTES (W_BYTES + 3 * A_STAGE_BYTES)   // 112640 -> 2 CTAs/SM

__device__ __forceinline__ uint32_t f2tf32(float f) {
    uint32_t u;
    asm("cvt.rna.tf32.f32 %0, %1;" : "=r"(u) : "f"(f));
    return u;
}

__device__ __forceinline__ void mma_tf32(float* d, const uint32_t* a,
                                         uint32_t b0, uint32_t b1) {
    asm volatile(
        "mma.sync.aligned.m16n8k8.row.col.f32.tf32.tf32.f32 "
        "{%0,%1,%2,%3}, {%4,%5,%6,%7}, {%8,%9}, {%0,%1,%2,%3};\n"
        : "+f"(d[0]), "+f"(d[1]), "+f"(d[2]), "+f"(d[3])
        : "r"(a[0]), "r"(a[1]), "r"(a[2]), "r"(a[3]), "r"(b0), "r"(b1));
}

__device__ __forceinline__ void cp_async16(uint32_t dst, const void* src) {
    asm volatile("cp.async.cg.shared.global [%0], [%1], 16;\n" :: "r"(dst), "l"(src));
}

__device__ __forceinline__ float tanh_fast(float x) {
    float y;
    asm("tanh.approx.f32 %0, %1;" : "=f"(y) : "f"(x));
    return y;
}
__device__ __forceinline__ float sigm(float x) {       // 0.5*tanh(x/2)+0.5
    return fmaf(tanh_fast(0.5f * x), 0.5f, 0.5f);
}

extern "C" __global__ void __launch_bounds__(THREADS, 2)
nctlstm_v2_kernel(const float* __restrict__ inter_times,
                  const float* __restrict__ h_ti,
                  const float* __restrict__ c_ti,
                  const float* __restrict__ cbar,
                  const float* __restrict__ W,
                  const float* __restrict__ bias,
                  float* __restrict__ out,
                  int Btot)
{
    extern __shared__ char smem[];
    const uint32_t sb = (uint32_t)__cvta_generic_to_shared(smem);
    uint4* wperm = reinterpret_cast<uint4*>(smem);

    const int tid  = threadIdx.x;
    const int warp = tid >> 5;       // 0..7 : m-group (16 rows each)
    const int lane = tid & 31;
    const int grp  = lane >> 2;      // 0..7
    const int tig  = lane & 3;       // 0..3

    const int o0  = blockIdx.x * BO;
    const int by  = blockIdx.y;
    const int nbt = Btot / BM;       // 512

    // ---- A stage loader: 1024 x 16B granules, 4 per thread ----
    auto load_chunk = [&](int tile, int ch, int s) {
        const uint32_t ab = sb + OFF_A + (uint32_t)s * A_STAGE_BYTES;
        const float* src = h_ti + (size_t)tile * BM * HH + ch * BK;
#pragma unroll
        for (int i = 0; i < 4; i++) {
            int idx = tid + i * THREADS;
            int r = idx >> 3, c4 = idx & 7;
            cp_async16(ab + (uint32_t)(r * (SSTR * 4) + c4 * 16),
                       src + (size_t)r * HH + c4 * 4);
        }
        asm volatile("cp.async.commit_group;\n");
    };

    // prologue: first two chunks in flight during W permute
    const int t0 = by;
    load_chunk(t0, 0, 0);
    load_chunk(t0, 1, 1);

    // ---- one-time W permute into fragment order (rna tf32) ----
    // unit u = (g*8 + ch)*2 + p ; lane holds cols k = ch*32+p*16+tig+{0,4,8,12}
    for (int u = warp; u < NG * NCHUNK * 2; u += 8) {
        const int p = u & 1, ch = (u >> 1) & 7, g = u >> 4;
        const int o = o0 + grp;
        const int k = ch * 32 + p * 16 + tig;
        const float* ws = W + ((size_t)g * HH + o) * HH + k;
        uint4 v;
        v.x = f2tf32(ws[0]);
        v.y = f2tf32(ws[4]);
        v.z = f2tf32(ws[8]);
        v.w = f2tf32(ws[12]);
        wperm[u * 32 + lane] = v;
    }

    // bias in registers (acc init)
    const int ocol = o0 + 2 * tig;
    float2 bv[NG];
#pragma unroll
    for (int g = 0; g < NG; g++)
        bv[g] = *reinterpret_cast<const float2*>(bias + (size_t)g * HH + ocol);

    const size_t BHtot = (size_t)Btot * HH;
    const int r0 = warp * 16 + grp;
    int s_cons = 0;

    for (int t = t0; t < nbt; t += GYS) {
        float acc[NG][4];
#pragma unroll
        for (int g = 0; g < NG; g++) {
            acc[g][0] = bv[g].x; acc[g][1] = bv[g].y;
            acc[g][2] = bv[g].x; acc[g][3] = bv[g].y;
        }

#pragma unroll 1
        for (int ch = 0; ch < NCHUNK; ch++) {
            asm volatile("cp.async.wait_group 1;\n");
            __syncthreads();

            // prefetch chunk gc+2 into the stage consumed last iteration
            {
                int c2 = ch + 2, t2 = t;
                if (c2 >= NCHUNK) { c2 -= NCHUNK; t2 += GYS; }
                int s_load = s_cons + 2; if (s_load >= 3) s_load -= 3;
                if (t2 < nbt) load_chunk(t2, c2, s_load);
                else          asm volatile("cp.async.commit_group;\n");
            }

            const float* hs = reinterpret_cast<const float*>(
                smem + OFF_A + s_cons * A_STAGE_BYTES);

#pragma unroll
            for (int p = 0; p < 2; p++) {
                uint32_t a[2][4];
#pragma unroll
                for (int q = 0; q < 2; q++) {
                    const int k0 = (2 * p + q) * 8;
                    a[q][0] = __float_as_uint(hs[r0 * SSTR + k0 + tig]);
                    a[q][1] = __float_as_uint(hs[(r0 + 8) * SSTR + k0 + tig]);
                    a[q][2] = __float_as_uint(hs[r0 * SSTR + k0 + tig + 4]);
                    a[q][3] = __float_as_uint(hs[(r0 + 8) * SSTR + k0 + tig + 4]);
                }
#pragma unroll
                for (int g = 0; g < NG; g++) {
                    const uint4 wf = wperm[((g * 8 + ch) * 2 + p) * 32 + lane];
                    mma_tf32(acc[g], a[0], wf.x, wf.y);
                    mma_tf32(acc[g], a[1], wf.z, wf.w);
                }
            }
            s_cons += 1; if (s_cons == 3) s_cons = 0;
        }

        // ---- fused epilogue (overlaps next tile's prefetched loads) ----
#pragma unroll
        for (int rs = 0; rs < 2; rs++) {
            const int b = t * BM + r0 + rs * 8;
            const float dt = __ldg(inter_times + b);
            const size_t base = (size_t)b * HH + ocol;
            const float2 cv = __ldcs(reinterpret_cast<const float2*>(c_ti + base));
            const float2 cb = __ldcs(reinterpret_cast<const float2*>(cbar + base));

            float2 r_o, r_h, r_c, r_cb, r_d;
#pragma unroll
            for (int j = 0; j < 2; j++) {
                const int ai = rs * 2 + j;
                const float gi  = acc[0][ai];
                const float gf  = acc[1][ai];
                const float go  = acc[2][ai];
                const float gib = acc[3][ai];
                const float gfb = acc[4][ai];
                const float gz  = acc[5][ai];
                const float gd  = acc[6][ai];

                const float i_g  = sigm(gi);
                const float f_g  = sigm(gf);
                const float o_g  = sigm(go);
                const float ib_g = sigm(gib);
                const float fb_g = sigm(gfb);
                const float z    = tanh_fast(gz);
                const float decay = fmaxf(gd, 0.0f)
                                  + __logf(1.0f + __expf(-fabsf(gd)));

                const float ct  = (j == 0) ? cv.x : cv.y;
                const float cbv = (j == 0) ? cb.x : cb.y;

                const float e       = __expf(-decay * dt);
                const float c_after = cbv + (ct - cbv) * e;
                const float c_new   = f_g * c_after + i_g * z;
                const float cb_new  = fb_g * cbv + ib_g * z;
                const float h_new   = o_g * tanh_fast(c_after);

                if (j == 0) { r_o.x = o_g; r_h.x = h_new; r_c.x = c_new; r_cb.x = cb_new; r_d.x = decay; }
                else        { r_o.y = o_g; r_h.y = h_new; r_c.y = c_new; r_cb.y = cb_new; r_d.y = decay; }
            }
            __stcs(reinterpret_cast<float2*>(out + 0 * BHtot + base), r_o);
            __stcs(reinterpret_cast<float2*>(out + 1 * BHtot + base), r_h);
            __stcs(reinterpret_cast<float2*>(out + 2 * BHtot + base), r_c);
            __stcs(reinterpret_cast<float2*>(out + 3 * BHtot + base), r_cb);
            __stcs(reinterpret_cast<float2*>(out + 4 * BHtot + base), r_d);
        }
    }
}

extern "C" void kernel_launch(void* const* d_in, const int* in_sizes, int n_in,
                              void* d_out, int out_size)
{
    const float* inter_times = (const float*)d_in[0];
    const float* h_ti        = (const float*)d_in[1];
    const float* c_ti        = (const float*)d_in[2];
    const float* cbar        = (const float*)d_in[3];
    const float* W           = (const float*)d_in[4];
    const float* bias        = (const float*)d_in[5];
    const int B = in_sizes[0];

    cudaFuncSetAttribute(nctlstm_v2_kernel,
                         cudaFuncAttributeMaxDynamicSharedMemorySize, SMEM_BYTES);

    dim3 grid(HH / BO, GYS);   // (32, 9) = 288 CTAs, all resident at 2/SM
    nctlstm_v2_kernel<<<grid, THREADS, SMEM_BYTES>>>(
        inter_times, h_ti, c_ti, cbar, W, bias, (float*)d_out, B);
}

// round 5
// speedup vs baseline: 1.2469x; 1.2469x over previous
#include <cuda_runtime.h>
#include <cstdint>
#include <cstddef>

// Legacy-path (mma.sync m16n8k8.tf32) fused NeuralCTLSTM, v3:
// Barrier-free warp-private pipelines. Warp tile m32 x n8 x 7 gates.
// BM=256 (8 warps x 32 rows), BO=8. W block (7x8x256 = 56KB) shared,
// pre-permuted once. Each warp cp.async-stages its own 32x32 A slice
// (3-stage private ring, per-thread wait_group) -> NO syncthreads in loop.

#define NG 7
#define HH 256
#define BM 256
#define BO 8
#define BK 32
#define NCHUNK 8
#define THREADS 256
#define GYS 18

#define W_BYTES (NG * NCHUNK * 2 * 512)        // 112 frag-units x 512B = 57344
#define A_STAGE_B 4608                          // 32 rows x 36 floats x 4B
#define A_WARP_B (3 * A_STAGE_B)                // 13824
#define SMEM_BYTES (W_BYTES + 8 * A_WARP_B)     // 167936

__device__ __forceinline__ uint32_t f2tf32(float f) {
    uint32_t u;
    asm("cvt.rna.tf32.f32 %0, %1;" : "=r"(u) : "f"(f));
    return u;
}

__device__ __forceinline__ void mma_tf32(float* d, const uint32_t* a,
                                         uint32_t b0, uint32_t b1) {
    asm volatile(
        "mma.sync.aligned.m16n8k8.row.col.f32.tf32.tf32.f32 "
        "{%0,%1,%2,%3}, {%4,%5,%6,%7}, {%8,%9}, {%0,%1,%2,%3};\n"
        : "+f"(d[0]), "+f"(d[1]), "+f"(d[2]), "+f"(d[3])
        : "r"(a[0]), "r"(a[1]), "r"(a[2]), "r"(a[3]), "r"(b0), "r"(b1));
}

__device__ __forceinline__ void cp_async16(uint32_t dst, const void* src) {
    asm volatile("cp.async.cg.shared.global [%0], [%1], 16;\n" :: "r"(dst), "l"(src));
}

__device__ __forceinline__ float tanh_fast(float x) {
    float y;
    asm("tanh.approx.f32 %0, %1;" : "=f"(y) : "f"(x));
    return y;
}
__device__ __forceinline__ float sigm(float x) {       // 0.5*tanh(x/2)+0.5
    return fmaf(tanh_fast(0.5f * x), 0.5f, 0.5f);
}

extern "C" __global__ void __launch_bounds__(THREADS, 1)
nctlstm_v3_kernel(const float* __restrict__ inter_times,
                  const float* __restrict__ h_ti,
                  const float* __restrict__ c_ti,
                  const float* __restrict__ cbar,
                  const float* __restrict__ W,
                  const float* __restrict__ bias,
                  float* __restrict__ out,
                  int Btot)
{
    extern __shared__ char smem[];
    const uint32_t sb = (uint32_t)__cvta_generic_to_shared(smem);
    uint4* wperm = reinterpret_cast<uint4*>(smem);

    const int tid  = threadIdx.x;
    const int warp = tid >> 5;       // 0..7 : owns rows warp*32 .. +31
    const int lane = tid & 31;
    const int grp  = lane >> 2;      // 0..7
    const int tig  = lane & 3;       // 0..3

    const int o0  = blockIdx.x * BO;
    const int by  = blockIdx.y;
    const int nbt = Btot / BM;       // 256

    const uint32_t warpA = sb + W_BYTES + (uint32_t)warp * A_WARP_B;
    const float*  warpAf = reinterpret_cast<const float*>(smem + W_BYTES + warp * A_WARP_B);

    // ---- warp-private A chunk loader: 32 rows x 32 cols, 8 cp.async/lane ----
    auto load_chunk = [&](int tile, int ch, int s) {
        const uint32_t ab = warpA + (uint32_t)s * A_STAGE_B;
        const float* src = h_ti + ((size_t)tile * BM + warp * 32) * HH + ch * BK;
#pragma unroll
        for (int i = 0; i < 8; i++) {
            const int idx = lane + i * 32;        // 0..255
            const int r = idx >> 3, c4 = idx & 7;
            cp_async16(ab + (uint32_t)(r * 144 + c4 * 16),
                       src + (size_t)r * HH + c4 * 4);
        }
        asm volatile("cp.async.commit_group;\n");
    };

    // prologue: first two chunks in flight during W permute
    const int t0 = by;
    load_chunk(t0, 0, 0);
    load_chunk(t0, 1, 1);

    // ---- one-time W permute into fragment order (rna tf32) ----
    // unit u = (g*8 + ch)*2 + p ; lane holds cols k = ch*32+p*16+tig+{0,4,8,12}
    for (int u = warp; u < NG * NCHUNK * 2; u += 8) {
        const int p = u & 1, ch = (u >> 1) & 7, g = u >> 4;
        const int o = o0 + grp;
        const int k = ch * 32 + p * 16 + tig;
        const float* ws = W + ((size_t)g * HH + o) * HH + k;
        uint4 v;
        v.x = f2tf32(ws[0]);
        v.y = f2tf32(ws[4]);
        v.z = f2tf32(ws[8]);
        v.w = f2tf32(ws[12]);
        wperm[u * 32 + lane] = v;
    }

    // bias in registers (acc init)
    const int ocol = o0 + 2 * tig;
    float2 bv[NG];
#pragma unroll
    for (int g = 0; g < NG; g++)
        bv[g] = *reinterpret_cast<const float2*>(bias + (size_t)g * HH + ocol);

    __syncthreads();   // W permute visible; ONLY block barrier in the kernel

    const size_t BHtot = (size_t)Btot * HH;
    int s_cons = 0;

    for (int t = t0; t < nbt; t += GYS) {
        float acc[NG][2][4];
#pragma unroll
        for (int g = 0; g < NG; g++)
#pragma unroll
            for (int mt = 0; mt < 2; mt++) {
                acc[g][mt][0] = bv[g].x; acc[g][mt][1] = bv[g].y;
                acc[g][mt][2] = bv[g].x; acc[g][mt][3] = bv[g].y;
            }

#pragma unroll 1
        for (int ch = 0; ch < NCHUNK; ch++) {
            asm volatile("cp.async.wait_group 1;\n");   // stage s_cons ready

            // prefetch chunk ch+2 (wrapping into next tile) into stage s_cons+2
            {
                int c2 = ch + 2, t2 = t;
                if (c2 >= NCHUNK) { c2 -= NCHUNK; t2 += GYS; }
                int s_load = s_cons + 2; if (s_load >= 3) s_load -= 3;
                if (t2 < nbt) load_chunk(t2, c2, s_load);
                else          asm volatile("cp.async.commit_group;\n");
            }

            const float* hs = warpAf + s_cons * (A_STAGE_B / 4);

#pragma unroll
            for (int p = 0; p < 2; p++) {
                uint32_t a[2][2][4];                    // [q][mt][frag]
#pragma unroll
                for (int q = 0; q < 2; q++) {
                    const int k0 = (2 * p + q) * 8;
#pragma unroll
                    for (int mt = 0; mt < 2; mt++) {
                        const int r = mt * 16 + grp;
                        a[q][mt][0] = __float_as_uint(hs[r * 36 + k0 + tig]);
                        a[q][mt][1] = __float_as_uint(hs[(r + 8) * 36 + k0 + tig]);
                        a[q][mt][2] = __float_as_uint(hs[r * 36 + k0 + tig + 4]);
                        a[q][mt][3] = __float_as_uint(hs[(r + 8) * 36 + k0 + tig + 4]);
                    }
                }
#pragma unroll
                for (int g = 0; g < NG; g++) {
                    const uint4 wf = wperm[((g * 8 + ch) * 2 + p) * 32 + lane];
                    mma_tf32(acc[g][0], a[0][0], wf.x, wf.y);
                    mma_tf32(acc[g][1], a[0][1], wf.x, wf.y);
                    mma_tf32(acc[g][0], a[1][0], wf.z, wf.w);
                    mma_tf32(acc[g][1], a[1][1], wf.z, wf.w);
                }
            }
            s_cons += 1; if (s_cons == 3) s_cons = 0;
        }

        // ---- fused epilogue (warp-local; overlaps other warps' MMAs) ----
#pragma unroll
        for (int mt = 0; mt < 2; mt++) {
#pragma unroll
            for (int rs = 0; rs < 2; rs++) {
                const int b = t * BM + warp * 32 + mt * 16 + grp + rs * 8;
                const float dt = __ldg(inter_times + b);
                const size_t base = (size_t)b * HH + ocol;
                const float2 cv = __ldcs(reinterpret_cast<const float2*>(c_ti + base));
                const float2 cb = __ldcs(reinterpret_cast<const float2*>(cbar + base));

                float2 r_o, r_h, r_c, r_cb, r_d;
#pragma unroll
                for (int j = 0; j < 2; j++) {
                    const int ai = rs * 2 + j;
                    const float gi  = acc[0][mt][ai];
                    const float gf  = acc[1][mt][ai];
                    const float go  = acc[2][mt][ai];
                    const float gib = acc[3][mt][ai];
                    const float gfb = acc[4][mt][ai];
                    const float gz  = acc[5][mt][ai];
                    const float gd  = acc[6][mt][ai];

                    const float i_g  = sigm(gi);
                    const float f_g  = sigm(gf);
                    const float o_g  = sigm(go);
                    const float ib_g = sigm(gib);
                    const float fb_g = sigm(gfb);
                    const float z    = tanh_fast(gz);
                    const float decay = fmaxf(gd, 0.0f)
                                      + __logf(1.0f + __expf(-fabsf(gd)));

                    const float ct  = (j == 0) ? cv.x : cv.y;
                    const float cbv = (j == 0) ? cb.x : cb.y;

                    const float e       = __expf(-decay * dt);
                    const float c_after = cbv + (ct - cbv) * e;
                    const float c_new   = f_g * c_after + i_g * z;
                    const float cb_new  = fb_g * cbv + ib_g * z;
                    const float h_new   = o_g * tanh_fast(c_after);

                    if (j == 0) { r_o.x = o_g; r_h.x = h_new; r_c.x = c_new; r_cb.x = cb_new; r_d.x = decay; }
                    else        { r_o.y = o_g; r_h.y = h_new; r_c.y = c_new; r_cb.y = cb_new; r_d.y = decay; }
                }
                __stcs(reinterpret_cast<float2*>(out + 0 * BHtot + base), r_o);
                __stcs(reinterpret_cast<float2*>(out + 1 * BHtot + base), r_h);
                __stcs(reinterpret_cast<float2*>(out + 2 * BHtot + base), r_c);
                __stcs(reinterpret_cast<float2*>(out + 3 * BHtot + base), r_cb);
                __stcs(reinterpret_cast<float2*>(out + 4 * BHtot + base), r_d);
            }
        }
    }
}

extern "C" void kernel_launch(void* const* d_in, const int* in_sizes, int n_in,
                              void* d_out, int out_size)
{
    const float* inter_times = (const float*)d_in[0];
    const float* h_ti        = (const float*)d_in[1];
    const float* c_ti        = (const float*)d_in[2];
    const float* cbar        = (const float*)d_in[3];
    const float* W           = (const float*)d_in[4];
    const float* bias        = (const float*)d_in[5];
    const int B = in_sizes[0];

    cudaFuncSetAttribute(nctlstm_v3_kernel,
                         cudaFuncAttributeMaxDynamicSharedMemorySize, SMEM_BYTES);

    dim3 grid(HH / BO, GYS);   // (32, 18) = 576 CTAs, ~14 b-tiles each
    nctlstm_v3_kernel<<<grid, THREADS, SMEM_BYTES>>>(
        inter_times, h_ti, c_ti, cbar, W, bias, (float*)d_out, B);
}

// round 6
// speedup vs baseline: 1.4792x; 1.1864x over previous
#include <cuda_runtime.h>
#include <cstdint>
#include <cstddef>

// Legacy-path (mma.sync m16n8k8.tf32) fused NeuralCTLSTM, v4:
// 12 warps/CTA (3 per SMSP), warp-private 2-stage cp.async pipelines,
// no block barriers in the main loop. Each CTA serves TWO o-blocks
// (warps 0-5 -> o-block 2bx, warps 6-11 -> 2bx+1), each with its own
// 56KB pre-permuted W region. Warp tile m32 x n8 x 7 gates.
// Grid (16, 9) = 144 CTAs = one clean wave.

#define NG 7
#define HH 256
#define BK 32
#define NCHUNK 8
#define THREADS 384
#define GYS 9
#define STREAMS (6 * GYS)          // 54 warp-streams per o-block

#define W_HALF (NG * NCHUNK * 2 * 512)      // 57344 per o-block
#define A_STAGE_B 4608                      // 32 rows x 36 floats x 4B
#define A_WARP_B (2 * A_STAGE_B)            // 9216
#define OFF_A (2 * W_HALF)                  // 114688
#define SMEM_BYTES (OFF_A + 12 * A_WARP_B)  // 225280

__device__ __forceinline__ uint32_t f2tf32(float f) {
    uint32_t u;
    asm("cvt.rna.tf32.f32 %0, %1;" : "=r"(u) : "f"(f));
    return u;
}

__device__ __forceinline__ void mma_tf32(float* d, const uint32_t* a,
                                         uint32_t b0, uint32_t b1) {
    asm volatile(
        "mma.sync.aligned.m16n8k8.row.col.f32.tf32.tf32.f32 "
        "{%0,%1,%2,%3}, {%4,%5,%6,%7}, {%8,%9}, {%0,%1,%2,%3};\n"
        : "+f"(d[0]), "+f"(d[1]), "+f"(d[2]), "+f"(d[3])
        : "r"(a[0]), "r"(a[1]), "r"(a[2]), "r"(a[3]), "r"(b0), "r"(b1));
}

__device__ __forceinline__ void cp_async16(uint32_t dst, const void* src) {
    asm volatile("cp.async.cg.shared.global [%0], [%1], 16;\n"
                 :: "r"(dst), "l"(src) : "memory");
}

__device__ __forceinline__ float tanh_fast(float x) {
    float y;
    asm("tanh.approx.f32 %0, %1;" : "=f"(y) : "f"(x));
    return y;
}
__device__ __forceinline__ float sigm(float x) {       // 0.5*tanh(x/2)+0.5
    return fmaf(tanh_fast(0.5f * x), 0.5f, 0.5f);
}

extern "C" __global__ void __launch_bounds__(THREADS, 1)
nctlstm_v4_kernel(const float* __restrict__ inter_times,
                  const float* __restrict__ h_ti,
                  const float* __restrict__ c_ti,
                  const float* __restrict__ cbar,
                  const float* __restrict__ W,
                  const float* __restrict__ bias,
                  float* __restrict__ out,
                  int Btot)
{
    extern __shared__ char smem[];
    const uint32_t sb = (uint32_t)__cvta_generic_to_shared(smem);

    const int tid  = threadIdx.x;
    const int warp = tid >> 5;       // 0..11
    const int lane = tid & 31;
    const int grp  = lane >> 2;      // 0..7
    const int tig  = lane & 3;       // 0..3
    const int sub  = (warp >= 6);    // which o-block half
    const int wl   = warp - sub * 6; // 0..5 within half

    const int o0 = (blockIdx.x * 2 + sub) * 8;
    const int stream = blockIdx.y * 6 + wl;     // 0..53
    const int nblk = Btot >> 5;                 // 2048 32-row blocks

    const uint4* wperm = reinterpret_cast<const uint4*>(smem + sub * W_HALF);
    uint4* wperm_w = reinterpret_cast<uint4*>(smem + sub * W_HALF);
    const uint32_t warpA = sb + OFF_A + (uint32_t)warp * A_WARP_B;
    const float*  warpAf = reinterpret_cast<const float*>(smem + OFF_A + warp * A_WARP_B);

    // ---- warp-private A chunk loader: 32 rows x 32 cols, 8 cp.async/lane ----
    auto load_chunk = [&](int rb, int ch, int s) {
        const uint32_t ab = warpA + (uint32_t)s * A_STAGE_B;
        const float* src = h_ti + ((size_t)rb << 5) * HH + ch * BK;
#pragma unroll
        for (int i = 0; i < 8; i++) {
            const int idx = lane + i * 32;        // 0..255
            const int r = idx >> 3, c4 = idx & 7;
            cp_async16(ab + (uint32_t)(r * 144 + c4 * 16),
                       src + (size_t)r * HH + c4 * 4);
        }
        asm volatile("cp.async.commit_group;\n" ::: "memory");
    };

    // prologue: first two chunks of first block in flight during W permute
    const int rb0 = stream;
    if (rb0 < nblk) {
        load_chunk(rb0, 0, 0);
        load_chunk(rb0, 1, 1);
    } else {
        asm volatile("cp.async.commit_group;\n" ::: "memory");
        asm volatile("cp.async.commit_group;\n" ::: "memory");
    }

    // ---- one-time W permute for this half (6 warps share the 112 units) ----
    for (int u = wl; u < NG * NCHUNK * 2; u += 6) {
        const int p = u & 1, ch = (u >> 1) & 7, g = u >> 4;
        const int o = o0 + grp;
        const int k = ch * 32 + p * 16 + tig;
        const float* ws = W + ((size_t)g * HH + o) * HH + k;
        uint4 v;
        v.x = f2tf32(ws[0]);
        v.y = f2tf32(ws[4]);
        v.z = f2tf32(ws[8]);
        v.w = f2tf32(ws[12]);
        wperm_w[u * 32 + lane] = v;
    }

    // bias in registers (acc init)
    const int ocol = o0 + 2 * tig;
    float2 bv[NG];
#pragma unroll
    for (int g = 0; g < NG; g++)
        bv[g] = *reinterpret_cast<const float2*>(bias + (size_t)g * HH + ocol);

    __syncthreads();   // W permute visible; only block barrier in the kernel

    const size_t BHtot = (size_t)Btot * HH;
    int s_cons = 0;

    for (int rb = rb0; rb < nblk; rb += STREAMS) {
        float acc[NG][2][4];
#pragma unroll
        for (int g = 0; g < NG; g++)
#pragma unroll
            for (int mt = 0; mt < 2; mt++) {
                acc[g][mt][0] = bv[g].x; acc[g][mt][1] = bv[g].y;
                acc[g][mt][2] = bv[g].x; acc[g][mt][3] = bv[g].y;
            }

#pragma unroll 1
        for (int ch = 0; ch < NCHUNK; ch++) {
            asm volatile("cp.async.wait_group 1;\n" ::: "memory");

            const float* hs = warpAf + s_cons * (A_STAGE_B / 4);

#pragma unroll
            for (int p = 0; p < 2; p++) {
                uint32_t a[2][2][4];                    // [q][mt][frag]
#pragma unroll
                for (int q = 0; q < 2; q++) {
                    const int k0 = (2 * p + q) * 8;
#pragma unroll
                    for (int mt = 0; mt < 2; mt++) {
                        const int r = mt * 16 + grp;
                        a[q][mt][0] = __float_as_uint(hs[r * 36 + k0 + tig]);
                        a[q][mt][1] = __float_as_uint(hs[(r + 8) * 36 + k0 + tig]);
                        a[q][mt][2] = __float_as_uint(hs[r * 36 + k0 + tig + 4]);
                        a[q][mt][3] = __float_as_uint(hs[(r + 8) * 36 + k0 + tig + 4]);
                    }
                }
#pragma unroll
                for (int g = 0; g < NG; g++) {
                    const uint4 wf = wperm[((g * 8 + ch) * 2 + p) * 32 + lane];
                    mma_tf32(acc[g][0], a[0][0], wf.x, wf.y);
                    mma_tf32(acc[g][1], a[0][1], wf.x, wf.y);
                    mma_tf32(acc[g][0], a[1][0], wf.z, wf.w);
                    mma_tf32(acc[g][1], a[1][1], wf.z, wf.w);
                }
            }

            // prefetch chunk ch+2 (wrapping into next block) into the stage
            // just consumed (safe: issued after all its LDS, GMEM writeback
            // is hundreds of cycles behind)
            {
                int c2 = ch + 2, r2 = rb;
                if (c2 >= NCHUNK) { c2 -= NCHUNK; r2 += STREAMS; }
                if (r2 < nblk) load_chunk(r2, c2, s_cons);
                else           asm volatile("cp.async.commit_group;\n" ::: "memory");
            }
            s_cons ^= 1;
        }

        // ---- fused epilogue (warp-local; overlaps other warps' MMAs) ----
#pragma unroll
        for (int mt = 0; mt < 2; mt++) {
#pragma unroll
            for (int rs = 0; rs < 2; rs++) {
                const int b = rb * 32 + mt * 16 + grp + rs * 8;
                const float dt = __ldg(inter_times + b);
                const size_t base = (size_t)b * HH + ocol;
                const float2 cv = __ldcs(reinterpret_cast<const float2*>(c_ti + base));
                const float2 cb = __ldcs(reinterpret_cast<const float2*>(cbar + base));

                float2 r_o, r_h, r_c, r_cb, r_d;
#pragma unroll
                for (int j = 0; j < 2; j++) {
                    const int ai = rs * 2 + j;
                    const float gi  = acc[0][mt][ai];
                    const float gf  = acc[1][mt][ai];
                    const float go  = acc[2][mt][ai];
                    const float gib = acc[3][mt][ai];
                    const float gfb = acc[4][mt][ai];
                    const float gz  = acc[5][mt][ai];
                    const float gd  = acc[6][mt][ai];

                    const float i_g  = sigm(gi);
                    const float f_g  = sigm(gf);
                    const float o_g  = sigm(go);
                    const float ib_g = sigm(gib);
                    const float fb_g = sigm(gfb);
                    const float z    = tanh_fast(gz);
                    const float decay = fmaxf(gd, 0.0f)
                                      + __logf(1.0f + __expf(-fabsf(gd)));

                    const float ct  = (j == 0) ? cv.x : cv.y;
                    const float cbv = (j == 0) ? cb.x : cb.y;

                    const float e       = __expf(-decay * dt);
                    const float c_after = cbv + (ct - cbv) * e;
                    const float c_new   = f_g * c_after + i_g * z;
                    const float cb_new  = fb_g * cbv + ib_g * z;
                    const float h_new   = o_g * tanh_fast(c_after);

                    if (j == 0) { r_o.x = o_g; r_h.x = h_new; r_c.x = c_new; r_cb.x = cb_new; r_d.x = decay; }
                    else        { r_o.y = o_g; r_h.y = h_new; r_c.y = c_new; r_cb.y = cb_new; r_d.y = decay; }
                }
                __stcs(reinterpret_cast<float2*>(out + 0 * BHtot + base), r_o);
                __stcs(reinterpret_cast<float2*>(out + 1 * BHtot + base), r_h);
                __stcs(reinterpret_cast<float2*>(out + 2 * BHtot + base), r_c);
                __stcs(reinterpret_cast<float2*>(out + 3 * BHtot + base), r_cb);
                __stcs(reinterpret_cast<float2*>(out + 4 * BHtot + base), r_d);
            }
        }
    }
}

extern "C" void kernel_launch(void* const* d_in, const int* in_sizes, int n_in,
                              void* d_out, int out_size)
{
    const float* inter_times = (const float*)d_in[0];
    const float* h_ti        = (const float*)d_in[1];
    const float* c_ti        = (const float*)d_in[2];
    const float* cbar        = (const float*)d_in[3];
    const float* W           = (const float*)d_in[4];
    const float* bias        = (const float*)d_in[5];
    const int B = in_sizes[0];

    cudaFuncSetAttribute(nctlstm_v4_kernel,
                         cudaFuncAttributeMaxDynamicSharedMemorySize, SMEM_BYTES);

    dim3 grid(16, GYS);   // 144 CTAs = one wave; 2 o-blocks per CTA
    nctlstm_v4_kernel<<<grid, THREADS, SMEM_BYTES>>>(
        inter_times, h_ti, c_ti, cbar, W, bias, (float*)d_out, B);
}

// round 7
// speedup vs baseline: 1.4964x; 1.0116x over previous
#include <cuda_runtime.h>
#include <cstdint>
#include <cstddef>

// Legacy-path (mma.sync m16n8k8.tf32) fused NeuralCTLSTM, v5:
// Warp tile m32 x n16 x 7 gates (112 HMMA / chunk / warp, 201 B smem/HMMA).
// 8 warps/CTA, warp-private 2-stage cp.async A rings, no loop barriers.
// CTA serves one 16-col o-block; W (7x16x256 = 112KB) resident, pre-permuted.
// Grid (16, 9) = 144 CTAs = one wave; 72 warp-streams per o-block.

#define NG 7
#define HH 256
#define BK 32
#define NCHUNK 8
#define THREADS 256
#define GYS 9
#define STREAMS (8 * GYS)                   // 72 warp-streams per o-block

#define W_BYTES (NG * NCHUNK * 2 * 2 * 512) // 224 frag-units x 512B = 114688
#define A_STAGE_B 4608                      // 32 rows x 36 floats x 4B
#define A_WARP_B (2 * A_STAGE_B)            // 9216
#define OFF_A W_BYTES
#define SMEM_BYTES (OFF_A + 8 * A_WARP_B)   // 188416

__device__ __forceinline__ uint32_t f2tf32(float f) {
    uint32_t u;
    asm("cvt.rna.tf32.f32 %0, %1;" : "=r"(u) : "f"(f));
    return u;
}

__device__ __forceinline__ void mma_tf32(float* d, const uint32_t* a,
                                         uint32_t b0, uint32_t b1) {
    asm volatile(
        "mma.sync.aligned.m16n8k8.row.col.f32.tf32.tf32.f32 "
        "{%0,%1,%2,%3}, {%4,%5,%6,%7}, {%8,%9}, {%0,%1,%2,%3};\n"
        : "+f"(d[0]), "+f"(d[1]), "+f"(d[2]), "+f"(d[3])
        : "r"(a[0]), "r"(a[1]), "r"(a[2]), "r"(a[3]), "r"(b0), "r"(b1));
}

__device__ __forceinline__ void cp_async16(uint32_t dst, const void* src) {
    asm volatile("cp.async.cg.shared.global [%0], [%1], 16;\n"
                 :: "r"(dst), "l"(src) : "memory");
}

__device__ __forceinline__ float tanh_fast(float x) {
    float y;
    asm("tanh.approx.f32 %0, %1;" : "=f"(y) : "f"(x));
    return y;
}
__device__ __forceinline__ float sigm(float x) {       // 0.5*tanh(x/2)+0.5
    return fmaf(tanh_fast(0.5f * x), 0.5f, 0.5f);
}

extern "C" __global__ void __launch_bounds__(THREADS, 1)
nctlstm_v5_kernel(const float* __restrict__ inter_times,
                  const float* __restrict__ h_ti,
                  const float* __restrict__ c_ti,
                  const float* __restrict__ cbar,
                  const float* __restrict__ W,
                  const float* __restrict__ bias,
                  float* __restrict__ out,
                  int Btot)
{
    extern __shared__ char smem[];
    const uint32_t sb = (uint32_t)__cvta_generic_to_shared(smem);

    const int tid  = threadIdx.x;
    const int warp = tid >> 5;       // 0..7
    const int lane = tid & 31;
    const int grp  = lane >> 2;      // 0..7
    const int tig  = lane & 3;       // 0..3

    const int o0 = blockIdx.x * 16;
    const int stream = blockIdx.y * 8 + warp;    // 0..71
    const int nblk = Btot >> 5;                  // 2048 32-row blocks

    const uint4* wperm = reinterpret_cast<const uint4*>(smem);
    uint4* wperm_w = reinterpret_cast<uint4*>(smem);
    const uint32_t warpA = sb + OFF_A + (uint32_t)warp * A_WARP_B;
    const float*  warpAf = reinterpret_cast<const float*>(smem + OFF_A + warp * A_WARP_B);

    // ---- warp-private A chunk loader: 32 rows x 32 cols, 8 cp.async/lane ----
    auto load_chunk = [&](int rb, int ch, int s) {
        const uint32_t ab = warpA + (uint32_t)s * A_STAGE_B;
        const float* src = h_ti + ((size_t)rb << 5) * HH + ch * BK;
#pragma unroll
        for (int i = 0; i < 8; i++) {
            const int idx = lane + i * 32;        // 0..255
            const int r = idx >> 3, c4 = idx & 7;
            cp_async16(ab + (uint32_t)(r * 144 + c4 * 16),
                       src + (size_t)r * HH + c4 * 4);
        }
        asm volatile("cp.async.commit_group;\n" ::: "memory");
    };

    // prologue: first two chunks of first block in flight during W permute
    const int rb0 = stream;
    load_chunk(rb0, 0, 0);
    load_chunk(rb0, 1, 1);

    // ---- one-time W permute (224 units, 8 warps cooperate) ----
    // unit u = (((g*8 + ch)*2 + p)*2 + nh); lane holds
    // W[g, o0+nh*8+grp, ch*32+p*16+tig+{0,4,8,12}] rna-rounded to tf32.
    for (int u = warp; u < NG * NCHUNK * 2 * 2; u += 8) {
        const int nh = u & 1, p = (u >> 1) & 1, ch = (u >> 2) & 7, g = u >> 5;
        const int o = o0 + nh * 8 + grp;
        const int k = ch * 32 + p * 16 + tig;
        const float* ws = W + ((size_t)g * HH + o) * HH + k;
        uint4 v;
        v.x = f2tf32(ws[0]);
        v.y = f2tf32(ws[4]);
        v.z = f2tf32(ws[8]);
        v.w = f2tf32(ws[12]);
        wperm_w[u * 32 + lane] = v;
    }

    // bias in registers (acc init)
    float2 bv[NG][2];
#pragma unroll
    for (int g = 0; g < NG; g++)
#pragma unroll
        for (int nh = 0; nh < 2; nh++)
            bv[g][nh] = *reinterpret_cast<const float2*>(
                bias + (size_t)g * HH + o0 + nh * 8 + 2 * tig);

    __syncthreads();   // W permute visible; only block barrier in the kernel

    const size_t BHtot = (size_t)Btot * HH;
    int s_cons = 0;

    for (int rb = rb0; rb < nblk; rb += STREAMS) {
        float acc[NG][2][2][4];          // [g][nh][mt][frag]
#pragma unroll
        for (int g = 0; g < NG; g++)
#pragma unroll
            for (int nh = 0; nh < 2; nh++)
#pragma unroll
                for (int mt = 0; mt < 2; mt++) {
                    acc[g][nh][mt][0] = bv[g][nh].x; acc[g][nh][mt][1] = bv[g][nh].y;
                    acc[g][nh][mt][2] = bv[g][nh].x; acc[g][nh][mt][3] = bv[g][nh].y;
                }

#pragma unroll 1
        for (int ch = 0; ch < NCHUNK; ch++) {
            asm volatile("cp.async.wait_group 1;\n" ::: "memory");

            const float* hs = warpAf + s_cons * (A_STAGE_B / 4);

            // load ALL A fragments for this chunk first (32 regs)
            uint32_t a[2][2][2][4];      // [p][q][mt][frag]
#pragma unroll
            for (int p = 0; p < 2; p++)
#pragma unroll
                for (int q = 0; q < 2; q++) {
                    const int k0 = (2 * p + q) * 8;
#pragma unroll
                    for (int mt = 0; mt < 2; mt++) {
                        const int r = mt * 16 + grp;
                        a[p][q][mt][0] = __float_as_uint(hs[r * 36 + k0 + tig]);
                        a[p][q][mt][1] = __float_as_uint(hs[(r + 8) * 36 + k0 + tig]);
                        a[p][q][mt][2] = __float_as_uint(hs[r * 36 + k0 + tig + 4]);
                        a[p][q][mt][3] = __float_as_uint(hs[(r + 8) * 36 + k0 + tig + 4]);
                    }
                }

            // prefetch chunk ch+2 into the stage just consumed
            {
                int c2 = ch + 2, r2 = rb;
                if (c2 >= NCHUNK) { c2 -= NCHUNK; r2 += STREAMS; }
                if (r2 < nblk) load_chunk(r2, c2, s_cons);
                else           asm volatile("cp.async.commit_group;\n" ::: "memory");
            }
            s_cons ^= 1;

            // 28 LDS.128 (W frags) + 112 HMMA
#pragma unroll
            for (int p = 0; p < 2; p++) {
#pragma unroll
                for (int g = 0; g < NG; g++) {
#pragma unroll
                    for (int nh = 0; nh < 2; nh++) {
                        const uint4 wf =
                            wperm[((((g * 8 + ch) * 2 + p) * 2) + nh) * 32 + lane];
                        mma_tf32(acc[g][nh][0], a[p][0][0], wf.x, wf.y);
                        mma_tf32(acc[g][nh][1], a[p][0][1], wf.x, wf.y);
                        mma_tf32(acc[g][nh][0], a[p][1][0], wf.z, wf.w);
                        mma_tf32(acc[g][nh][1], a[p][1][1], wf.z, wf.w);
                    }
                }
            }
        }

        // ---- fused epilogue (warp-local; overlaps other warps' MMAs) ----
#pragma unroll
        for (int mt = 0; mt < 2; mt++) {
#pragma unroll
            for (int rs = 0; rs < 2; rs++) {
                const int b = rb * 32 + mt * 16 + grp + rs * 8;
                const float dt = __ldg(inter_times + b);
#pragma unroll
                for (int nh = 0; nh < 2; nh++) {
                    const size_t base = (size_t)b * HH + o0 + nh * 8 + 2 * tig;
                    const float2 cv = __ldcs(reinterpret_cast<const float2*>(c_ti + base));
                    const float2 cb = __ldcs(reinterpret_cast<const float2*>(cbar + base));

                    float2 r_o, r_h, r_c, r_cb, r_d;
#pragma unroll
                    for (int j = 0; j < 2; j++) {
                        const int ai = rs * 2 + j;
                        const float gi  = acc[0][nh][mt][ai];
                        const float gf  = acc[1][nh][mt][ai];
                        const float go  = acc[2][nh][mt][ai];
                        const float gib = acc[3][nh][mt][ai];
                        const float gfb = acc[4][nh][mt][ai];
                        const float gz  = acc[5][nh][mt][ai];
                        const float gd  = acc[6][nh][mt][ai];

                        const float i_g  = sigm(gi);
                        const float f_g  = sigm(gf);
                        const float o_g  = sigm(go);
                        const float ib_g = sigm(gib);
                        const float fb_g = sigm(gfb);
                        const float z    = tanh_fast(gz);
                        const float decay = fmaxf(gd, 0.0f)
                                          + __logf(1.0f + __expf(-fabsf(gd)));

                        const float ct  = (j == 0) ? cv.x : cv.y;
                        const float cbv = (j == 0) ? cb.x : cb.y;

                        const float e       = __expf(-decay * dt);
                        const float c_after = cbv + (ct - cbv) * e;
                        const float c_new   = f_g * c_after + i_g * z;
                        const float cb_new  = fb_g * cbv + ib_g * z;
                        const float h_new   = o_g * tanh_fast(c_after);

                        if (j == 0) { r_o.x = o_g; r_h.x = h_new; r_c.x = c_new; r_cb.x = cb_new; r_d.x = decay; }
                        else        { r_o.y = o_g; r_h.y = h_new; r_c.y = c_new; r_cb.y = cb_new; r_d.y = decay; }
                    }
                    __stcs(reinterpret_cast<float2*>(out + 0 * BHtot + base), r_o);
                    __stcs(reinterpret_cast<float2*>(out + 1 * BHtot + base), r_h);
                    __stcs(reinterpret_cast<float2*>(out + 2 * BHtot + base), r_c);
                    __stcs(reinterpret_cast<float2*>(out + 3 * BHtot + base), r_cb);
                    __stcs(reinterpret_cast<float2*>(out + 4 * BHtot + base), r_d);
                }
            }
        }
    }
}

extern "C" void kernel_launch(void* const* d_in, const int* in_sizes, int n_in,
                              void* d_out, int out_size)
{
    const float* inter_times = (const float*)d_in[0];
    const float* h_ti        = (const float*)d_in[1];
    const float* c_ti        = (const float*)d_in[2];
    const float* cbar        = (const float*)d_in[3];
    const float* W           = (const float*)d_in[4];
    const float* bias        = (const float*)d_in[5];
    const int B = in_sizes[0];

    cudaFuncSetAttribute(nctlstm_v5_kernel,
                         cudaFuncAttributeMaxDynamicSharedMemorySize, SMEM_BYTES);

    dim3 grid(16, GYS);   // 144 CTAs = one wave; one 16-col o-block per CTA
    nctlstm_v5_kernel<<<grid, THREADS, SMEM_BYTES>>>(
        inter_times, h_ti, c_ti, cbar, W, bias, (float*)d_out, B);
}